// round 3
// baseline (speedup 1.0000x reference)
#include <cuda_runtime.h>
#include <cuda_bf16.h>
#include <math.h>

// Problem dims (fixed)
#define BSZ  32
#define TLEN 512
#define DIN  512
#define HN   1024
#define G4H  (4*HN)   // 4096

#define WPAD 1028      // padded row stride (floats) for W in smem: conflict-free LDS.128
#define NBLK 128       // persistent grid size (<= 148 SMs, 1 CTA/SM)

// ---------------- scratch (device globals; no allocation allowed) ----------------
__device__ float g_xg[(size_t)TLEN * BSZ * G4H];   // [T][B][4H]  256 MB
__device__ float g_hseq[(size_t)BSZ * TLEN * HN];  // [B][T][H]    64 MB
__device__ float g_Wp0[(size_t)G4H * HN];          // packed Wh0   16 MB
__device__ float g_Wp1[(size_t)G4H * HN];          // packed Wh1   16 MB
__device__ float g_h[2][BSZ * HN];                 // ping-pong h
__device__ unsigned g_cnt;                          // grid barrier counter
__device__ volatile unsigned g_gen;                 // grid barrier generation

// ---------------- grid-wide barrier (persistent kernel, co-resident CTAs) ----------------
__device__ __forceinline__ void grid_bar() {
    __threadfence();          // make this thread's writes visible device-wide
    __syncthreads();
    if (threadIdx.x == 0) {
        unsigned my = g_gen;
        if (atomicAdd(&g_cnt, 1u) == (unsigned)(gridDim.x - 1)) {
            g_cnt = 0;
            __threadfence();
            g_gen = my + 1;
        } else {
            while (g_gen == my) { }
        }
        __threadfence();
    }
    __syncthreads();
}

// ---------------- pack Wh [K=1024][4096] -> Wp[row][k] ----------------
// row = nb*32 + gate*8 + nl  for column c = gate*1024 + nb*8 + nl.
__global__ void pack_wh_kernel(const float* __restrict__ Wh, float* __restrict__ Wp) {
    __shared__ float tile[32][33];
    const int c0 = blockIdx.x * 32;
    const int k0 = blockIdx.y * 32;
    const int tx = threadIdx.x, ty = threadIdx.y;  // 32 x 8
#pragma unroll
    for (int i = 0; i < 32; i += 8)
        tile[ty + i][tx] = Wh[(size_t)(k0 + ty + i) * G4H + c0 + tx];
    __syncthreads();
#pragma unroll
    for (int i = 0; i < 32; i += 8) {
        int c  = c0 + ty + i;
        int g  = c >> 10;
        int r  = c & (HN - 1);
        int row = ((r >> 3) << 5) + (g << 3) + (r & 7);
        Wp[(size_t)row * HN + k0 + tx] = tile[tx][ty + i];
    }
}

// ---------------- input projection GEMM: C = A @ Bw + bias ----------------
// A: [16384 x K] row-major (row m = b*T + t), Bw: [K x 4096] row-major.
// C written as [T][B][4H]: out row = t*32 + b.
__global__ void __launch_bounds__(256) gemm_xg_kernel(
    const float* __restrict__ A, const float* __restrict__ Bw,
    const float* __restrict__ bias, float* __restrict__ C, int K)
{
    __shared__ float As[8][128];
    __shared__ float Bs[8][128];
    const int tid = threadIdx.x;
    const int bx = blockIdx.x, by = blockIdx.y;
    const float* Ab = A + (size_t)by * 128 * K;
    const float* Bb = Bw + (size_t)bx * 128;
    const int aRow = tid >> 1, aCol = (tid & 1) << 2;
    const int bRow = tid >> 5, bCol = (tid & 31) << 2;
    const int tx = tid & 15, ty = tid >> 4;
    float acc[8][8] = {};
    for (int k0 = 0; k0 < K; k0 += 8) {
        float4 a4 = *(const float4*)(Ab + (size_t)aRow * K + k0 + aCol);
        As[aCol + 0][aRow] = a4.x; As[aCol + 1][aRow] = a4.y;
        As[aCol + 2][aRow] = a4.z; As[aCol + 3][aRow] = a4.w;
        *(float4*)&Bs[bRow][bCol] =
            *(const float4*)(Bb + (size_t)(k0 + bRow) * G4H + bCol);
        __syncthreads();
#pragma unroll
        for (int k = 0; k < 8; k++) {
            float ar[8], br[8];
            *(float4*)&ar[0] = *(const float4*)&As[k][ty * 8];
            *(float4*)&ar[4] = *(const float4*)&As[k][ty * 8 + 4];
            *(float4*)&br[0] = *(const float4*)&Bs[k][tx * 8];
            *(float4*)&br[4] = *(const float4*)&Bs[k][tx * 8 + 4];
#pragma unroll
            for (int i = 0; i < 8; i++)
#pragma unroll
                for (int j = 0; j < 8; j++) acc[i][j] += ar[i] * br[j];
        }
        __syncthreads();
    }
#pragma unroll
    for (int i = 0; i < 8; i++) {
        int m = by * 128 + ty * 8 + i;
        int orow = (m & (TLEN - 1)) * BSZ + (m >> 9);   // t*32 + b
        float* Cp = C + (size_t)orow * G4H + bx * 128 + tx * 8;
        const float* bp = bias + bx * 128 + tx * 8;
#pragma unroll
        for (int j = 0; j < 8; j++) Cp[j] = acc[i][j] + bp[j];
    }
}

// ---------------- persistent LSTM layer: all 512 steps in one kernel ----------------
// Grid: 128 blocks x 256 threads, 1 CTA/SM (co-resident -> software grid barrier ok).
// Block nb owns output cols n in [nb*8, nb*8+8) = packed W rows [nb*32, nb*32+32).
// Thread (wq = warp 0..7, jj = lane): accumulates acc[q] = dot(W_row_jj, h[b=wq*4+q]).
// Epilogue: shuffle-transpose gates; each lane handles one (b, n) element; cell
// state c lives in a register for the whole layer.
extern __shared__ float s_mem[];
__global__ void __launch_bounds__(256, 1) lstm_layer_persistent(
    const float* __restrict__ xg,    // [T][B][4H]
    const float* __restrict__ Wp,    // packed [4096][1024]
    float* __restrict__ hA,          // ping
    float* __restrict__ hB,          // pong
    float* __restrict__ outb)        // [B][T][H]
{
    const int tid = threadIdx.x;
    const int jj  = tid & 31;
    const int wq  = tid >> 5;
    const int nb  = blockIdx.x;

    float* Wsm = s_mem;                       // 32 rows x WPAD floats
    float* hsA = s_mem + 32 * WPAD;           // 32 x 132
    float* hsB = hsA + 32 * 132;

    // ---- load this block's W slice into smem (once per layer) ----
    {
        const float4* Wg = (const float4*)(Wp + (size_t)nb * 32 * HN);
#pragma unroll
        for (int it = 0; it < 32; it++) {
            int i4  = it * 256 + tid;         // float4 index in [0, 8192)
            int row = i4 >> 8;                // /256 float4 per row
            int col = i4 & 255;
            *(float4*)(Wsm + (size_t)row * WPAD + col * 4) = Wg[i4];
        }
    }

    // ---- init: zero h ping buffer slice; c in register ----
    const int nl  = jj & 7;
    const int gq  = jj >> 3;
    const int myn = nb * 8 + nl;              // this lane's output col
    const int myb = wq * 4 + gq;              // this lane's batch
    {
        int b0 = tid >> 3, n0 = nb * 8 + (tid & 7);
        hA[b0 * HN + n0] = 0.f;
    }
    float creg = 0.f;
    __syncthreads();
    grid_bar();

    const float4* Wrow = (const float4*)(Wsm + (size_t)jj * WPAD);

    for (int t = 0; t < TLEN; t++) {
        const float* h_in  = (t & 1) ? hB : hA;
        float*       h_out = (t & 1) ? hA : hB;
        const float* xg_t  = xg + (size_t)t * BSZ * G4H;

        // prefetch this lane's 4 gate inputs (DRAM latency hidden by k-loop)
        const float* xp = xg_t + (size_t)myb * G4H + myn;
        float xvi = xp[0];
        float xvf = xp[HN];
        float xvg = xp[2 * HN];
        float xvo = xp[3 * HN];

        float acc[4] = {0.f, 0.f, 0.f, 0.f};

        // stage chunk 0 (L2 reads: h is written by other SMs; bypass L1)
#pragma unroll
        for (int i = 0; i < 4; i++) {
            int row = wq + i * 8;
            float4 v = __ldcg((const float4*)&h_in[(size_t)row * HN + jj * 4]);
            *(float4*)&hsA[row * 132 + jj * 4] = v;
        }
        __syncthreads();

#pragma unroll
        for (int c8 = 0; c8 < 8; c8++) {
            float4 nxt[4];
            if (c8 < 7) {
#pragma unroll
                for (int i = 0; i < 4; i++) {
                    int row = wq + i * 8;
                    nxt[i] = __ldcg((const float4*)
                        &h_in[(size_t)row * HN + (c8 + 1) * 128 + jj * 4]);
                }
            }
            const float* hcur = (c8 & 1) ? hsB : hsA;
            const float4* wr = Wrow + c8 * 32;
            const float4* h0 = (const float4*)&hcur[(wq * 4 + 0) * 132];
            const float4* h1 = (const float4*)&hcur[(wq * 4 + 1) * 132];
            const float4* h2 = (const float4*)&hcur[(wq * 4 + 2) * 132];
            const float4* h3 = (const float4*)&hcur[(wq * 4 + 3) * 132];
#pragma unroll
            for (int kk = 0; kk < 32; kk++) {
                float4 w = wr[kk];
                float4 a = h0[kk];
                acc[0] += w.x * a.x + w.y * a.y + w.z * a.z + w.w * a.w;
                float4 b = h1[kk];
                acc[1] += w.x * b.x + w.y * b.y + w.z * b.z + w.w * b.w;
                float4 c = h2[kk];
                acc[2] += w.x * c.x + w.y * c.y + w.z * c.z + w.w * c.w;
                float4 d = h3[kk];
                acc[3] += w.x * d.x + w.y * d.y + w.z * d.z + w.w * d.w;
            }
            if (c8 < 7) {
                float* hnxt = (c8 & 1) ? hsA : hsB;
#pragma unroll
                for (int i = 0; i < 4; i++)
                    *(float4*)&hnxt[(wq + i * 8) * 132 + jj * 4] = nxt[i];
                __syncthreads();
            }
        }

        // gate exchange: lane (gq, nl) collects gates for batch group gq, col nl.
        const unsigned FULL = 0xffffffffu;
        float gi = 0.f, gf = 0.f, gg = 0.f, go = 0.f;
#pragma unroll
        for (int q = 0; q < 4; q++) {
            float t0 = __shfl_sync(FULL, acc[q], nl);
            float t1 = __shfl_sync(FULL, acc[q], nl + 8);
            float t2 = __shfl_sync(FULL, acc[q], nl + 16);
            float t3 = __shfl_sync(FULL, acc[q], nl + 24);
            if (gq == q) { gi = t0; gf = t1; gg = t2; go = t3; }
        }
        gi += xvi; gf += xvf; gg += xvg; go += xvo;

        float si = 1.f / (1.f + expf(-gi));
        float sf = 1.f / (1.f + expf(-gf));
        float so = 1.f / (1.f + expf(-go));
        creg = sf * creg + si * tanhf(gg);
        float hv = so * tanhf(creg);

        h_out[(size_t)myb * HN + myn] = hv;
        outb[(size_t)myb * (TLEN * HN) + (size_t)t * HN + myn] = hv;

        grid_bar();
    }
}

// ---------------- driver (6 graph nodes) ----------------
extern "C" void kernel_launch(void* const* d_in, const int* in_sizes, int n_in,
                              void* d_out, int out_size) {
    const float* x   = (const float*)d_in[0];
    const float* Wx0 = (const float*)d_in[1];
    const float* Wh0 = (const float*)d_in[2];
    const float* b0  = (const float*)d_in[3];
    const float* Wx1 = (const float*)d_in[4];
    const float* Wh1 = (const float*)d_in[5];
    const float* b1  = (const float*)d_in[6];
    float* out = (float*)d_out;

    float *xg, *hseq, *wp0, *wp1, *hbuf;
    cudaGetSymbolAddress((void**)&xg,   g_xg);
    cudaGetSymbolAddress((void**)&hseq, g_hseq);
    cudaGetSymbolAddress((void**)&wp0,  g_Wp0);
    cudaGetSymbolAddress((void**)&wp1,  g_Wp1);
    cudaGetSymbolAddress((void**)&hbuf, g_h);

    const int SMEMB = (32 * WPAD + 2 * 32 * 132) * (int)sizeof(float);
    cudaFuncSetAttribute(lstm_layer_persistent,
                         cudaFuncAttributeMaxDynamicSharedMemorySize, SMEMB);

    const dim3 tpb(32, 8);
    pack_wh_kernel<<<dim3(G4H / 32, HN / 32), tpb>>>(Wh0, wp0);
    pack_wh_kernel<<<dim3(G4H / 32, HN / 32), tpb>>>(Wh1, wp1);

    // layer 0: input projection then persistent recurrence -> hseq [B][T][H]
    gemm_xg_kernel<<<dim3(G4H / 128, (BSZ * TLEN) / 128), 256>>>(x, Wx0, b0, xg, DIN);
    lstm_layer_persistent<<<NBLK, 256, SMEMB>>>(
        xg, wp0, hbuf, hbuf + BSZ * HN, hseq);

    // layer 1: input projection (hseq as [B*T, H]) then recurrence -> out
    gemm_xg_kernel<<<dim3(G4H / 128, (BSZ * TLEN) / 128), 256>>>(hseq, Wx1, b1, xg, HN);
    lstm_layer_persistent<<<NBLK, 256, SMEMB>>>(
        xg, wp1, hbuf, hbuf + BSZ * HN, out);
}

// round 4
// speedup vs baseline: 1.1683x; 1.1683x over previous
#include <cuda_runtime.h>
#include <cuda_bf16.h>
#include <math.h>

// Problem dims (fixed)
#define BSZ  32
#define TLEN 512
#define DIN  512
#define HN   1024
#define G4H  (4*HN)   // 4096

#define WPAD 1028      // padded row stride (floats) for W in smem
#define NBLK 128       // persistent grid size (1 CTA/SM)

// ---------------- scratch (device globals; no allocation allowed) ----------------
__device__ float g_xg[(size_t)TLEN * BSZ * G4H];   // [T][B][4H]  256 MB
__device__ float g_hseq[(size_t)BSZ * TLEN * HN];  // [B][T][H]    64 MB
__device__ float g_Wp0[(size_t)G4H * HN];          // packed Wh0   16 MB
__device__ float g_Wp1[(size_t)G4H * HN];          // packed Wh1   16 MB
__device__ float g_h[2][BSZ * HN];                 // ping-pong h
__device__ unsigned g_cnt;                          // grid barrier counter
__device__ volatile unsigned g_gen;                 // grid barrier generation

// ---------------- grid-wide barrier (persistent kernel, co-resident CTAs) ----------------
__device__ __forceinline__ void grid_bar() {
    __threadfence();
    __syncthreads();
    if (threadIdx.x == 0) {
        unsigned my = g_gen;
        if (atomicAdd(&g_cnt, 1u) == (unsigned)(gridDim.x - 1)) {
            g_cnt = 0;
            __threadfence();
            g_gen = my + 1;
        } else {
            while (g_gen == my) { }
        }
        __threadfence();
    }
    __syncthreads();
}

// ---------------- tf32 helpers ----------------
__device__ __forceinline__ unsigned f2tf(float f) {
    unsigned u; asm("cvt.rna.tf32.f32 %0, %1;" : "=r"(u) : "f"(f)); return u;
}
__device__ __forceinline__ uint4 f2tf4(float4 v) {
    uint4 u; u.x = f2tf(v.x); u.y = f2tf(v.y); u.z = f2tf(v.z); u.w = f2tf(v.w);
    return u;
}
__device__ __forceinline__ void mma_tf32(float* c, const unsigned* a, const unsigned* b) {
    asm volatile(
        "mma.sync.aligned.m16n8k8.row.col.f32.tf32.tf32.f32 "
        "{%0,%1,%2,%3}, {%4,%5,%6,%7}, {%8,%9}, {%0,%1,%2,%3};\n"
        : "+f"(c[0]), "+f"(c[1]), "+f"(c[2]), "+f"(c[3])
        : "r"(a[0]), "r"(a[1]), "r"(a[2]), "r"(a[3]), "r"(b[0]), "r"(b[1]));
}

// ---------------- pack Wh [K=1024][4096] -> Wp[row][k] ----------------
__global__ void pack_wh_kernel(const float* __restrict__ Wh, float* __restrict__ Wp) {
    __shared__ float tile[32][33];
    const int c0 = blockIdx.x * 32;
    const int k0 = blockIdx.y * 32;
    const int tx = threadIdx.x, ty = threadIdx.y;  // 32 x 8
#pragma unroll
    for (int i = 0; i < 32; i += 8)
        tile[ty + i][tx] = Wh[(size_t)(k0 + ty + i) * G4H + c0 + tx];
    __syncthreads();
#pragma unroll
    for (int i = 0; i < 32; i += 8) {
        int c  = c0 + ty + i;
        int g  = c >> 10;
        int r  = c & (HN - 1);
        int row = ((r >> 3) << 5) + (g << 3) + (r & 7);
        Wp[(size_t)row * HN + k0 + tx] = tile[tx][ty + i];
    }
}

// ---------------- tf32 tensor-core input projection: C = A @ Bw + bias ----------------
// A: [16384 x K] row-major (row m = b*T + t), Bw: [K x 4096] row-major.
// C written as [T][B][4H]: out row = (m & 511)*32 + (m >> 9).
// Block tile 128x128, 8 warps (warp tile 64x32), K-tile 32.
__global__ void __launch_bounds__(256, 1) gemm_xg_tc(
    const float* __restrict__ A, const float* __restrict__ Bw,
    const float* __restrict__ bias, float* __restrict__ C, int K)
{
    __shared__ unsigned As[128][32];    // [m][k], col swizzled: k ^ ((m&7)<<2)
    __shared__ unsigned Bs[32][136];    // [k][n], pad 8

    const int tid = threadIdx.x;
    const int bx = blockIdx.x;          // n tile (0..31)
    const int by = blockIdx.y;          // m tile (0..127)
    const int wid = tid >> 5;
    const int lane = tid & 31;
    const int g = lane >> 2, tg = lane & 3;
    const int wm = wid & 1, wn = wid >> 1;
    const int m0w = wm * 64, n0w = wn * 32;
    const int KT = K >> 5;

    float acc[4][4][4];
#pragma unroll
    for (int a = 0; a < 4; a++)
#pragma unroll
        for (int b = 0; b < 4; b++)
#pragma unroll
            for (int cix = 0; cix < 4; cix++) acc[a][b][cix] = 0.f;

    float4 aP[4], bP[4];
    const int aRow[4] = { (0*256 + tid) >> 3, (1*256 + tid) >> 3,
                          (2*256 + tid) >> 3, (3*256 + tid) >> 3 };
    const int aKc = tid & 7;
    const int bK[4] = { (0*256 + tid) >> 5, (1*256 + tid) >> 5,
                        (2*256 + tid) >> 5, (3*256 + tid) >> 5 };
    const int bNc = tid & 31;

    // prefetch tile 0
#pragma unroll
    for (int it = 0; it < 4; it++) {
        aP[it] = *(const float4*)(A + (size_t)(by * 128 + aRow[it]) * K + aKc * 4);
        bP[it] = *(const float4*)(Bw + (size_t)bK[it] * G4H + bx * 128 + bNc * 4);
    }
#pragma unroll
    for (int it = 0; it < 4; it++) {
        *(uint4*)&As[aRow[it]][(aKc * 4) ^ ((aRow[it] & 7) << 2)] = f2tf4(aP[it]);
        *(uint4*)&Bs[bK[it]][bNc * 4] = f2tf4(bP[it]);
    }
    __syncthreads();

    for (int kt = 0; kt < KT; kt++) {
        if (kt + 1 < KT) {
            const int k0 = (kt + 1) * 32;
#pragma unroll
            for (int it = 0; it < 4; it++) {
                aP[it] = *(const float4*)(A + (size_t)(by * 128 + aRow[it]) * K + k0 + aKc * 4);
                bP[it] = *(const float4*)(Bw + (size_t)(k0 + bK[it]) * G4H + bx * 128 + bNc * 4);
            }
        }
#pragma unroll
        for (int s = 0; s < 4; s++) {
            unsigned af[4][4], bf[4][2];
            const int c0 = (8 * s + tg) ^ (g << 2);
            const int c1 = c0 ^ 4;
#pragma unroll
            for (int mb = 0; mb < 4; mb++) {
                int m = m0w + mb * 16 + g;
                af[mb][0] = As[m][c0];
                af[mb][1] = As[m + 8][c0];
                af[mb][2] = As[m][c1];
                af[mb][3] = As[m + 8][c1];
            }
#pragma unroll
            for (int nb = 0; nb < 4; nb++) {
                bf[nb][0] = Bs[8 * s + tg][n0w + nb * 8 + g];
                bf[nb][1] = Bs[8 * s + tg + 4][n0w + nb * 8 + g];
            }
#pragma unroll
            for (int mb = 0; mb < 4; mb++)
#pragma unroll
                for (int nb = 0; nb < 4; nb++)
                    mma_tf32(acc[mb][nb], af[mb], bf[nb]);
        }
        __syncthreads();
        if (kt + 1 < KT) {
#pragma unroll
            for (int it = 0; it < 4; it++) {
                *(uint4*)&As[aRow[it]][(aKc * 4) ^ ((aRow[it] & 7) << 2)] = f2tf4(aP[it]);
                *(uint4*)&Bs[bK[it]][bNc * 4] = f2tf4(bP[it]);
            }
            __syncthreads();
        }
    }

    // epilogue: bias add + scatter to [T][B][4H]
#pragma unroll
    for (int mb = 0; mb < 4; mb++) {
        int m1 = by * 128 + m0w + mb * 16 + g;
        int m2 = m1 + 8;
        size_t r1 = (size_t)(((m1 & 511) << 5) + (m1 >> 9)) * G4H;
        size_t r2 = (size_t)(((m2 & 511) << 5) + (m2 >> 9)) * G4H;
#pragma unroll
        for (int nb = 0; nb < 4; nb++) {
            int n = bx * 128 + n0w + nb * 8 + 2 * tg;
            float2 bb = *(const float2*)(bias + n);
            float2 o1 = { acc[mb][nb][0] + bb.x, acc[mb][nb][1] + bb.y };
            float2 o2 = { acc[mb][nb][2] + bb.x, acc[mb][nb][3] + bb.y };
            *(float2*)(C + r1 + n) = o1;
            *(float2*)(C + r2 + n) = o2;
        }
    }
}

// ---------------- persistent LSTM layer: all 512 steps in one kernel ----------------
extern __shared__ float s_mem[];
__global__ void __launch_bounds__(256, 1) lstm_layer_persistent(
    const float* __restrict__ xg,    // [T][B][4H]
    const float* __restrict__ Wp,    // packed [4096][1024]
    float* __restrict__ hA,          // ping
    float* __restrict__ hB,          // pong
    float* __restrict__ outb)        // [B][T][H]
{
    const int tid = threadIdx.x;
    const int jj  = tid & 31;
    const int wq  = tid >> 5;
    const int nb  = blockIdx.x;

    float* Wsm = s_mem;                       // 32 rows x WPAD floats
    float* hsA = s_mem + 32 * WPAD;           // 32 x 132
    float* hsB = hsA + 32 * 132;

    {
        const float4* Wg = (const float4*)(Wp + (size_t)nb * 32 * HN);
#pragma unroll
        for (int it = 0; it < 32; it++) {
            int i4  = it * 256 + tid;
            int row = i4 >> 8;
            int col = i4 & 255;
            *(float4*)(Wsm + (size_t)row * WPAD + col * 4) = Wg[i4];
        }
    }

    const int nl  = jj & 7;
    const int gq  = jj >> 3;
    const int myn = nb * 8 + nl;
    const int myb = wq * 4 + gq;
    {
        int b0 = tid >> 3, n0 = nb * 8 + (tid & 7);
        hA[b0 * HN + n0] = 0.f;
    }
    float creg = 0.f;
    __syncthreads();
    grid_bar();

    const float4* Wrow = (const float4*)(Wsm + (size_t)jj * WPAD);

    for (int t = 0; t < TLEN; t++) {
        const float* h_in  = (t & 1) ? hB : hA;
        float*       h_out = (t & 1) ? hA : hB;
        const float* xg_t  = xg + (size_t)t * BSZ * G4H;

        const float* xp = xg_t + (size_t)myb * G4H + myn;
        float xvi = xp[0];
        float xvf = xp[HN];
        float xvg = xp[2 * HN];
        float xvo = xp[3 * HN];

        float acc[4] = {0.f, 0.f, 0.f, 0.f};

#pragma unroll
        for (int i = 0; i < 4; i++) {
            int row = wq + i * 8;
            float4 v = __ldcg((const float4*)&h_in[(size_t)row * HN + jj * 4]);
            *(float4*)&hsA[row * 132 + jj * 4] = v;
        }
        __syncthreads();

#pragma unroll
        for (int c8 = 0; c8 < 8; c8++) {
            float4 nxt[4];
            if (c8 < 7) {
#pragma unroll
                for (int i = 0; i < 4; i++) {
                    int row = wq + i * 8;
                    nxt[i] = __ldcg((const float4*)
                        &h_in[(size_t)row * HN + (c8 + 1) * 128 + jj * 4]);
                }
            }
            const float* hcur = (c8 & 1) ? hsB : hsA;
            const float4* wr = Wrow + c8 * 32;
            const float4* h0 = (const float4*)&hcur[(wq * 4 + 0) * 132];
            const float4* h1 = (const float4*)&hcur[(wq * 4 + 1) * 132];
            const float4* h2 = (const float4*)&hcur[(wq * 4 + 2) * 132];
            const float4* h3 = (const float4*)&hcur[(wq * 4 + 3) * 132];
#pragma unroll
            for (int kk = 0; kk < 32; kk++) {
                float4 w = wr[kk];
                float4 a = h0[kk];
                acc[0] += w.x * a.x + w.y * a.y + w.z * a.z + w.w * a.w;
                float4 b = h1[kk];
                acc[1] += w.x * b.x + w.y * b.y + w.z * b.z + w.w * b.w;
                float4 c = h2[kk];
                acc[2] += w.x * c.x + w.y * c.y + w.z * c.z + w.w * c.w;
                float4 d = h3[kk];
                acc[3] += w.x * d.x + w.y * d.y + w.z * d.z + w.w * d.w;
            }
            if (c8 < 7) {
                float* hnxt = (c8 & 1) ? hsA : hsB;
#pragma unroll
                for (int i = 0; i < 4; i++)
                    *(float4*)&hnxt[(wq + i * 8) * 132 + jj * 4] = nxt[i];
                __syncthreads();
            }
        }

        const unsigned FULL = 0xffffffffu;
        float gi = 0.f, gf = 0.f, gg = 0.f, go = 0.f;
#pragma unroll
        for (int q = 0; q < 4; q++) {
            float t0 = __shfl_sync(FULL, acc[q], nl);
            float t1 = __shfl_sync(FULL, acc[q], nl + 8);
            float t2 = __shfl_sync(FULL, acc[q], nl + 16);
            float t3 = __shfl_sync(FULL, acc[q], nl + 24);
            if (gq == q) { gi = t0; gf = t1; gg = t2; go = t3; }
        }
        gi += xvi; gf += xvf; gg += xvg; go += xvo;

        float si = 1.f / (1.f + expf(-gi));
        float sf = 1.f / (1.f + expf(-gf));
        float so = 1.f / (1.f + expf(-go));
        creg = sf * creg + si * tanhf(gg);
        float hv = so * tanhf(creg);

        h_out[(size_t)myb * HN + myn] = hv;
        outb[(size_t)myb * (TLEN * HN) + (size_t)t * HN + myn] = hv;

        grid_bar();
    }
}

// ---------------- driver (6 graph nodes) ----------------
extern "C" void kernel_launch(void* const* d_in, const int* in_sizes, int n_in,
                              void* d_out, int out_size) {
    const float* x   = (const float*)d_in[0];
    const float* Wx0 = (const float*)d_in[1];
    const float* Wh0 = (const float*)d_in[2];
    const float* b0  = (const float*)d_in[3];
    const float* Wx1 = (const float*)d_in[4];
    const float* Wh1 = (const float*)d_in[5];
    const float* b1  = (const float*)d_in[6];
    float* out = (float*)d_out;

    float *xg, *hseq, *wp0, *wp1, *hbuf;
    cudaGetSymbolAddress((void**)&xg,   g_xg);
    cudaGetSymbolAddress((void**)&hseq, g_hseq);
    cudaGetSymbolAddress((void**)&wp0,  g_Wp0);
    cudaGetSymbolAddress((void**)&wp1,  g_Wp1);
    cudaGetSymbolAddress((void**)&hbuf, g_h);

    const int SMEMB = (32 * WPAD + 2 * 32 * 132) * (int)sizeof(float);
    cudaFuncSetAttribute(lstm_layer_persistent,
                         cudaFuncAttributeMaxDynamicSharedMemorySize, SMEMB);

    const dim3 tpb(32, 8);
    pack_wh_kernel<<<dim3(G4H / 32, HN / 32), tpb>>>(Wh0, wp0);
    pack_wh_kernel<<<dim3(G4H / 32, HN / 32), tpb>>>(Wh1, wp1);

    // layer 0: input projection then persistent recurrence -> hseq [B][T][H]
    gemm_xg_tc<<<dim3(G4H / 128, (BSZ * TLEN) / 128), 256>>>(x, Wx0, b0, xg, DIN);
    lstm_layer_persistent<<<NBLK, 256, SMEMB>>>(
        xg, wp0, hbuf, hbuf + BSZ * HN, hseq);

    // layer 1: input projection (hseq as [B*T, H]) then recurrence -> out
    gemm_xg_tc<<<dim3(G4H / 128, (BSZ * TLEN) / 128), 256>>>(hseq, Wx1, b1, xg, HN);
    lstm_layer_persistent<<<NBLK, 256, SMEMB>>>(
        xg, wp1, hbuf, hbuf + BSZ * HN, out);
}

// round 5
// speedup vs baseline: 1.3788x; 1.1802x over previous
#include <cuda_runtime.h>
#include <cuda_bf16.h>
#include <math.h>

// Problem dims (fixed)
#define BSZ  32
#define TLEN 512
#define DIN  512
#define HN   1024
#define G4H  (4*HN)   // 4096

#define WPAD 1028      // W smem row stride (floats): 4112B % 128 = 16 -> conflict-free LDS.128
#define HQS  260       // h quarter-row stride (floats)
#define RSTR 36        // reduction col stride (floats): 144B % 128 = 16, 16B aligned
#define NBLK 128       // persistent grid size (1 CTA/SM)

// ---------------- scratch (device globals; no allocation allowed) ----------------
__device__ float g_xg[(size_t)TLEN * BSZ * G4H];   // [T][B][4H]  256 MB
__device__ float g_hseq[(size_t)BSZ * TLEN * HN];  // [B][T][H]    64 MB
__device__ float g_Wp0[(size_t)G4H * HN];          // packed Wh0   16 MB
__device__ float g_Wp1[(size_t)G4H * HN];          // packed Wh1   16 MB
__device__ float g_h[2][BSZ * HN];                 // ping-pong h
__device__ unsigned g_cnt;                          // grid barrier counter
__device__ volatile unsigned g_gen;                 // grid barrier generation

// ---------------- grid-wide barrier ----------------
__device__ __forceinline__ void grid_bar() {
    __threadfence();
    __syncthreads();
    if (threadIdx.x == 0) {
        unsigned my = g_gen;
        if (atomicAdd(&g_cnt, 1u) == (unsigned)(gridDim.x - 1)) {
            g_cnt = 0;
            __threadfence();
            g_gen = my + 1;
        } else {
            while (g_gen == my) { }
        }
        __threadfence();
    }
    __syncthreads();
}

// ---------------- packed dual-fp32 FMA (FFMA2; sm_100+) ----------------
__device__ __forceinline__ void ffma2(unsigned long long& d,
                                      unsigned long long a,
                                      unsigned long long b) {
    asm("fma.rn.f32x2 %0, %1, %2, %3;" : "=l"(d) : "l"(a), "l"(b), "l"(d));
}
__device__ __forceinline__ float pairsum(unsigned long long v) {
    return __uint_as_float((unsigned)(v & 0xffffffffull)) +
           __uint_as_float((unsigned)(v >> 32));
}

// ---------------- tf32 helpers ----------------
__device__ __forceinline__ unsigned f2tf(float f) {
    unsigned u; asm("cvt.rna.tf32.f32 %0, %1;" : "=r"(u) : "f"(f)); return u;
}
__device__ __forceinline__ uint4 f2tf4(float4 v) {
    uint4 u; u.x = f2tf(v.x); u.y = f2tf(v.y); u.z = f2tf(v.z); u.w = f2tf(v.w);
    return u;
}
__device__ __forceinline__ void mma_tf32(float* c, const unsigned* a, const unsigned* b) {
    asm volatile(
        "mma.sync.aligned.m16n8k8.row.col.f32.tf32.tf32.f32 "
        "{%0,%1,%2,%3}, {%4,%5,%6,%7}, {%8,%9}, {%0,%1,%2,%3};\n"
        : "+f"(c[0]), "+f"(c[1]), "+f"(c[2]), "+f"(c[3])
        : "r"(a[0]), "r"(a[1]), "r"(a[2]), "r"(a[3]), "r"(b[0]), "r"(b[1]));
}

// ---------------- pack Wh [K=1024][4096] -> Wp[row][k] ----------------
// Within block nb, packed row (gate*8 + nl) <- column gate*1024 + nb*8 + nl.
__global__ void pack_wh_kernel(const float* __restrict__ Wh, float* __restrict__ Wp) {
    __shared__ float tile[32][33];
    const int c0 = blockIdx.x * 32;
    const int k0 = blockIdx.y * 32;
    const int tx = threadIdx.x, ty = threadIdx.y;  // 32 x 8
#pragma unroll
    for (int i = 0; i < 32; i += 8)
        tile[ty + i][tx] = Wh[(size_t)(k0 + ty + i) * G4H + c0 + tx];
    __syncthreads();
#pragma unroll
    for (int i = 0; i < 32; i += 8) {
        int c  = c0 + ty + i;
        int g  = c >> 10;
        int r  = c & (HN - 1);
        int row = ((r >> 3) << 5) + (g << 3) + (r & 7);
        Wp[(size_t)row * HN + k0 + tx] = tile[tx][ty + i];
    }
}

// ---------------- tf32 tensor-core input projection (unchanged from R4) ----------------
__global__ void __launch_bounds__(256, 1) gemm_xg_tc(
    const float* __restrict__ A, const float* __restrict__ Bw,
    const float* __restrict__ bias, float* __restrict__ C, int K)
{
    __shared__ unsigned As[128][32];    // [m][k], col swizzled: k ^ ((m&7)<<2)
    __shared__ unsigned Bs[32][136];    // [k][n], pad 8

    const int tid = threadIdx.x;
    const int bx = blockIdx.x;
    const int by = blockIdx.y;
    const int wid = tid >> 5;
    const int lane = tid & 31;
    const int g = lane >> 2, tg = lane & 3;
    const int wm = wid & 1, wn = wid >> 1;
    const int m0w = wm * 64, n0w = wn * 32;
    const int KT = K >> 5;

    float acc[4][4][4];
#pragma unroll
    for (int a = 0; a < 4; a++)
#pragma unroll
        for (int b = 0; b < 4; b++)
#pragma unroll
            for (int cix = 0; cix < 4; cix++) acc[a][b][cix] = 0.f;

    float4 aP[4], bP[4];
    const int aRow[4] = { (0*256 + tid) >> 3, (1*256 + tid) >> 3,
                          (2*256 + tid) >> 3, (3*256 + tid) >> 3 };
    const int aKc = tid & 7;
    const int bK[4] = { (0*256 + tid) >> 5, (1*256 + tid) >> 5,
                        (2*256 + tid) >> 5, (3*256 + tid) >> 5 };
    const int bNc = tid & 31;

#pragma unroll
    for (int it = 0; it < 4; it++) {
        aP[it] = *(const float4*)(A + (size_t)(by * 128 + aRow[it]) * K + aKc * 4);
        bP[it] = *(const float4*)(Bw + (size_t)bK[it] * G4H + bx * 128 + bNc * 4);
    }
#pragma unroll
    for (int it = 0; it < 4; it++) {
        *(uint4*)&As[aRow[it]][(aKc * 4) ^ ((aRow[it] & 7) << 2)] = f2tf4(aP[it]);
        *(uint4*)&Bs[bK[it]][bNc * 4] = f2tf4(bP[it]);
    }
    __syncthreads();

    for (int kt = 0; kt < KT; kt++) {
        if (kt + 1 < KT) {
            const int k0 = (kt + 1) * 32;
#pragma unroll
            for (int it = 0; it < 4; it++) {
                aP[it] = *(const float4*)(A + (size_t)(by * 128 + aRow[it]) * K + k0 + aKc * 4);
                bP[it] = *(const float4*)(Bw + (size_t)(k0 + bK[it]) * G4H + bx * 128 + bNc * 4);
            }
        }
#pragma unroll
        for (int s = 0; s < 4; s++) {
            unsigned af[4][4], bf[4][2];
            const int c0 = (8 * s + tg) ^ (g << 2);
            const int c1 = c0 ^ 4;
#pragma unroll
            for (int mb = 0; mb < 4; mb++) {
                int m = m0w + mb * 16 + g;
                af[mb][0] = As[m][c0];
                af[mb][1] = As[m + 8][c0];
                af[mb][2] = As[m][c1];
                af[mb][3] = As[m + 8][c1];
            }
#pragma unroll
            for (int nb = 0; nb < 4; nb++) {
                bf[nb][0] = Bs[8 * s + tg][n0w + nb * 8 + g];
                bf[nb][1] = Bs[8 * s + tg + 4][n0w + nb * 8 + g];
            }
#pragma unroll
            for (int mb = 0; mb < 4; mb++)
#pragma unroll
                for (int nb = 0; nb < 4; nb++)
                    mma_tf32(acc[mb][nb], af[mb], bf[nb]);
        }
        __syncthreads();
        if (kt + 1 < KT) {
#pragma unroll
            for (int it = 0; it < 4; it++) {
                *(uint4*)&As[aRow[it]][(aKc * 4) ^ ((aRow[it] & 7) << 2)] = f2tf4(aP[it]);
                *(uint4*)&Bs[bK[it]][bNc * 4] = f2tf4(bP[it]);
            }
            __syncthreads();
        }
    }

#pragma unroll
    for (int mb = 0; mb < 4; mb++) {
        int m1 = by * 128 + m0w + mb * 16 + g;
        int m2 = m1 + 8;
        size_t r1 = (size_t)(((m1 & 511) << 5) + (m1 >> 9)) * G4H;
        size_t r2 = (size_t)(((m2 & 511) << 5) + (m2 >> 9)) * G4H;
#pragma unroll
        for (int nb = 0; nb < 4; nb++) {
            int n = bx * 128 + n0w + nb * 8 + 2 * tg;
            float2 bb = *(const float2*)(bias + n);
            float2 o1 = { acc[mb][nb][0] + bb.x, acc[mb][nb][1] + bb.y };
            float2 o2 = { acc[mb][nb][2] + bb.x, acc[mb][nb][3] + bb.y };
            *(float2*)(C + r1 + n) = o1;
            *(float2*)(C + r2 + n) = o2;
        }
    }
}

// ---------------- persistent LSTM layer: FFMA2 k-major version ----------------
// 128 blocks x 256 threads, 1 CTA/SM. Block nb owns 8 n-cols (32 gate-cols =
// packed W rows nb*32..+32). Warp wq owns k-slice (32 k per quarter, 128 total).
// Lane jj = gate-col. Each lane accumulates ALL 32 batches as packed (k-even,
// k-odd) f32x2 pairs -> 2048 FFMA2/lane/step. Cross-warp reduction 8->4->gates
// in smem aliased over the h staging buffer.
extern __shared__ float s_mem[];
__global__ void __launch_bounds__(256, 1) lstm_layer_persistent(
    const float* __restrict__ xg,    // [T][B][4H]
    const float* __restrict__ Wp,    // packed [4096][1024]
    float* __restrict__ hA,          // ping
    float* __restrict__ hB,          // pong
    float* __restrict__ outb)        // [B][T][H]
{
    const int tid = threadIdx.x;
    const int jj  = tid & 31;
    const int wq  = tid >> 5;
    const int nb  = blockIdx.x;

    float* Wsm = s_mem;                       // 32 x WPAD
    float* hq0 = s_mem + 32 * WPAD;           // 32 x HQS (quarter ping)
    float* hq1 = hq0 + 32 * HQS;              // 32 x HQS (quarter pong)
    float* red = hq0;                         // [4][32][RSTR], aliased (18.4KB)

    // ---- load this block's W slice into smem (once per layer) ----
    {
        const float4* Wg = (const float4*)(Wp + (size_t)nb * 32 * HN);
#pragma unroll
        for (int it = 0; it < 32; it++) {
            int i4  = it * 256 + tid;
            int row = i4 >> 8;
            int col = i4 & 255;
            *(float4*)(Wsm + (size_t)row * WPAD + col * 4) = Wg[i4];
        }
    }

    const int nl  = jj & 7;
    const int bq  = jj >> 3;
    const int myn = nb * 8 + nl;              // this lane's output col
    const int myb = wq * 4 + bq;              // this lane's batch
    {
        int b0 = tid >> 3, n0 = nb * 8 + (tid & 7);
        hA[b0 * HN + n0] = 0.f;
    }
    float creg = 0.f;
    __syncthreads();
    grid_bar();

    for (int t = 0; t < TLEN; t++) {
        const float* h_in  = (t & 1) ? hB : hA;
        float*       h_out = (t & 1) ? hA : hB;
        const float* xg_t  = xg + (size_t)t * BSZ * G4H;

        // prefetch this lane's 4 gate inputs
        const float* xp = xg_t + (size_t)myb * G4H + myn;
        float xvi = xp[0];
        float xvf = xp[HN];
        float xvg = xp[2 * HN];
        float xvo = xp[3 * HN];

        unsigned long long acc2[32];
#pragma unroll
        for (int b = 0; b < 32; b++) acc2[b] = 0ull;

        // prefetch quarter 0 into registers (L2 reads; h written by other SMs)
        float4 p[8];
#pragma unroll
        for (int i = 0; i < 8; i++) {
            int idx = i * 256 + tid;
            int b = idx >> 6, k4 = idx & 63;
            p[i] = __ldcg((const float4*)&h_in[(size_t)b * HN + k4 * 4]);
        }

#pragma unroll
        for (int q = 0; q < 4; q++) {
            float* hs = (q & 1) ? hq1 : hq0;
            __syncthreads();   // staging buffer free
#pragma unroll
            for (int i = 0; i < 8; i++) {
                int idx = i * 256 + tid;
                int b = idx >> 6, k4 = idx & 63;
                *(float4*)&hs[b * HQS + k4 * 4] = p[i];
            }
            __syncthreads();
            if (q < 3) {
#pragma unroll
                for (int i = 0; i < 8; i++) {
                    int idx = i * 256 + tid;
                    int b = idx >> 6, k4 = idx & 63;
                    p[i] = __ldcg((const float4*)
                        &h_in[(size_t)b * HN + (q + 1) * 256 + k4 * 4]);
                }
            }
            // compute: lane jj x warp k-slice [q*256 + wq*32, +32)
            const ulonglong2* Wk = (const ulonglong2*)
                (Wsm + (size_t)jj * WPAD + q * 256 + wq * 32);
            const char* hrow = (const char*)(hs + wq * 32);
#pragma unroll
            for (int g = 0; g < 8; g++) {
                ulonglong2 wv = Wk[g];
                const char* hp = hrow + g * 16;
#pragma unroll
                for (int b = 0; b < 32; b++) {
                    ulonglong2 hv = *(const ulonglong2*)(hp + b * (HQS * 4));
                    ffma2(acc2[b], wv.x, hv.x);
                    ffma2(acc2[b], wv.y, hv.y);
                }
            }
        }

        // collapse packed pairs
        float av[32];
#pragma unroll
        for (int b = 0; b < 32; b++) av[b] = pairsum(acc2[b]);

        // reduction: warps 0-3 write, warps 4-7 accumulate
        __syncthreads();
        if (wq < 4) {
            float* rp = &red[(wq * 32 + jj) * RSTR];
#pragma unroll
            for (int b4 = 0; b4 < 8; b4++) {
                float4 v = { av[b4*4], av[b4*4+1], av[b4*4+2], av[b4*4+3] };
                *(float4*)&rp[b4 * 4] = v;
            }
        }
        __syncthreads();
        if (wq >= 4) {
            float* rp = &red[((wq - 4) * 32 + jj) * RSTR];
#pragma unroll
            for (int b4 = 0; b4 < 8; b4++) {
                float4 v = *(const float4*)&rp[b4 * 4];
                v.x += av[b4*4];   v.y += av[b4*4+1];
                v.z += av[b4*4+2]; v.w += av[b4*4+3];
                *(float4*)&rp[b4 * 4] = v;
            }
        }
        __syncthreads();

        // gates for this lane's (myb, myn)
        float gi = xvi, gf = xvf, gg = xvg, go = xvo;
#pragma unroll
        for (int s = 0; s < 4; s++) {
            gi += red[(s * 32 +      nl) * RSTR + myb];
            gf += red[(s * 32 +  8 + nl) * RSTR + myb];
            gg += red[(s * 32 + 16 + nl) * RSTR + myb];
            go += red[(s * 32 + 24 + nl) * RSTR + myb];
        }

        float si = 1.f / (1.f + expf(-gi));
        float sf = 1.f / (1.f + expf(-gf));
        float so = 1.f / (1.f + expf(-go));
        creg = sf * creg + si * tanhf(gg);
        float hv = so * tanhf(creg);

        h_out[(size_t)myb * HN + myn] = hv;
        outb[(size_t)myb * (TLEN * HN) + (size_t)t * HN + myn] = hv;

        grid_bar();
    }
}

// ---------------- driver (6 graph nodes) ----------------
extern "C" void kernel_launch(void* const* d_in, const int* in_sizes, int n_in,
                              void* d_out, int out_size) {
    const float* x   = (const float*)d_in[0];
    const float* Wx0 = (const float*)d_in[1];
    const float* Wh0 = (const float*)d_in[2];
    const float* b0  = (const float*)d_in[3];
    const float* Wx1 = (const float*)d_in[4];
    const float* Wh1 = (const float*)d_in[5];
    const float* b1  = (const float*)d_in[6];
    float* out = (float*)d_out;

    float *xg, *hseq, *wp0, *wp1, *hbuf;
    cudaGetSymbolAddress((void**)&xg,   g_xg);
    cudaGetSymbolAddress((void**)&hseq, g_hseq);
    cudaGetSymbolAddress((void**)&wp0,  g_Wp0);
    cudaGetSymbolAddress((void**)&wp1,  g_Wp1);
    cudaGetSymbolAddress((void**)&hbuf, g_h);

    const int SMEMB = (32 * WPAD + 2 * 32 * HQS) * (int)sizeof(float);
    cudaFuncSetAttribute(lstm_layer_persistent,
                         cudaFuncAttributeMaxDynamicSharedMemorySize, SMEMB);

    const dim3 tpb(32, 8);
    pack_wh_kernel<<<dim3(G4H / 32, HN / 32), tpb>>>(Wh0, wp0);
    pack_wh_kernel<<<dim3(G4H / 32, HN / 32), tpb>>>(Wh1, wp1);

    // layer 0: input projection then persistent recurrence -> hseq [B][T][H]
    gemm_xg_tc<<<dim3(G4H / 128, (BSZ * TLEN) / 128), 256>>>(x, Wx0, b0, xg, DIN);
    lstm_layer_persistent<<<NBLK, 256, SMEMB>>>(
        xg, wp0, hbuf, hbuf + BSZ * HN, hseq);

    // layer 1: input projection (hseq as [B*T, H]) then recurrence -> out
    gemm_xg_tc<<<dim3(G4H / 128, (BSZ * TLEN) / 128), 256>>>(hseq, Wx1, b1, xg, HN);
    lstm_layer_persistent<<<NBLK, 256, SMEMB>>>(
        xg, wp1, hbuf, hbuf + BSZ * HN, out);
}

// round 8
// speedup vs baseline: 1.4620x; 1.0604x over previous
#include <cuda_runtime.h>
#include <cuda_bf16.h>
#include <math.h>
#include <stdint.h>

// Problem dims (fixed)
#define BSZ  32
#define TLEN 512
#define DIN  512
#define HN   1024
#define G4H  (4*HN)   // 4096

#define WPAD 1028      // W smem row stride (floats) for recurrence
#define HQS  260       // h quarter-row stride (floats)
#define RSTR 36        // reduction col stride (floats)
#define NBLK 128       // persistent grid size (1 CTA/SM)

// GEMM staging (bytes)
#define ABYT 16384     // As: 128 rows x 128B
#define BBYT 17408     // Bs: 32 rows x 544B (136 floats, pad 8)
#define STG  (ABYT + BBYT)

// ---------------- scratch (device globals; no allocation allowed) ----------------
__device__ float g_xg[(size_t)TLEN * BSZ * G4H];   // [T][B][4H]  256 MB
__device__ float g_hseq[(size_t)BSZ * TLEN * HN];  // [B][T][H]    64 MB
__device__ float g_Wp0[(size_t)G4H * HN];          // packed Wh0 (recurrence)
__device__ float g_Wp1[(size_t)G4H * HN];          // packed Wh1
__device__ float g_h[2][BSZ * HN];                 // ping-pong h
__device__ unsigned g_cnt;
__device__ volatile unsigned g_gen;
__device__ float g_Atf[(size_t)16384 * 1024];      // tf32-rounded A   64 MB
__device__ float g_Btf[(size_t)1024 * G4H];        // tf32-rounded W   16 MB

// ---------------- grid-wide barrier ----------------
__device__ __forceinline__ void grid_bar() {
    __threadfence();
    __syncthreads();
    if (threadIdx.x == 0) {
        unsigned my = g_gen;
        if (atomicAdd(&g_cnt, 1u) == (unsigned)(gridDim.x - 1)) {
            g_cnt = 0;
            __threadfence();
            g_gen = my + 1;
        } else {
            while (g_gen == my) { }
        }
        __threadfence();
    }
    __syncthreads();
}

// ---------------- packed dual-fp32 FMA (recurrence) ----------------
__device__ __forceinline__ void ffma2(unsigned long long& d,
                                      unsigned long long a,
                                      unsigned long long b) {
    asm("fma.rn.f32x2 %0, %1, %2, %3;" : "=l"(d) : "l"(a), "l"(b), "l"(d));
}
__device__ __forceinline__ float pairsum(unsigned long long v) {
    return __uint_as_float((unsigned)(v & 0xffffffffull)) +
           __uint_as_float((unsigned)(v >> 32));
}

// ---------------- tf32 + cp.async helpers ----------------
__device__ __forceinline__ unsigned f2tf(float f) {
    unsigned u; asm("cvt.rna.tf32.f32 %0, %1;" : "=r"(u) : "f"(f)); return u;
}
__device__ __forceinline__ void mma_tf32(float* c, const unsigned* a, const unsigned* b) {
    asm volatile(
        "mma.sync.aligned.m16n8k8.row.col.f32.tf32.tf32.f32 "
        "{%0,%1,%2,%3}, {%4,%5,%6,%7}, {%8,%9}, {%0,%1,%2,%3};\n"
        : "+f"(c[0]), "+f"(c[1]), "+f"(c[2]), "+f"(c[3])
        : "r"(a[0]), "r"(a[1]), "r"(a[2]), "r"(a[3]), "r"(b[0]), "r"(b[1]));
}
__device__ __forceinline__ uint32_t smem_u32(const void* p) {
    uint32_t a;
    asm("{ .reg .u64 t; cvta.to.shared.u64 t, %1; cvt.u32.u64 %0, t; }"
        : "=r"(a) : "l"(p));
    return a;
}
__device__ __forceinline__ void cp16(uint32_t d, const void* s) {
    asm volatile("cp.async.cg.shared.global [%0], [%1], 16;" :: "r"(d), "l"(s));
}
__device__ __forceinline__ void cp_commit() {
    asm volatile("cp.async.commit_group;" ::: "memory");
}

// ---------------- dummy kernel (shifts ncu -s 5 capture onto the GEMM) ----------------
__global__ void warm_kernel() {}

// ---------------- prep: round fp32 -> tf32 in place layout ----------------
__global__ void cvt_tf32_kernel(const float* __restrict__ in,
                                float* __restrict__ out, int n4) {
    int i = blockIdx.x * blockDim.x + threadIdx.x;
    if (i >= n4) return;
    float4 v = *(const float4*)(in + (size_t)i * 4);
    v.x = __uint_as_float(f2tf(v.x));
    v.y = __uint_as_float(f2tf(v.y));
    v.z = __uint_as_float(f2tf(v.z));
    v.w = __uint_as_float(f2tf(v.w));
    *(float4*)(out + (size_t)i * 4) = v;
}

// ---------------- pack Wh [K=1024][4096] -> Wp[row][k] (recurrence) ----------------
__global__ void pack_wh_kernel(const float* __restrict__ Wh, float* __restrict__ Wp) {
    __shared__ float tile[32][33];
    const int c0 = blockIdx.x * 32;
    const int k0 = blockIdx.y * 32;
    const int tx = threadIdx.x, ty = threadIdx.y;
#pragma unroll
    for (int i = 0; i < 32; i += 8)
        tile[ty + i][tx] = Wh[(size_t)(k0 + ty + i) * G4H + c0 + tx];
    __syncthreads();
#pragma unroll
    for (int i = 0; i < 32; i += 8) {
        int c  = c0 + ty + i;
        int g  = c >> 10;
        int r  = c & (HN - 1);
        int row = ((r >> 3) << 5) + (g << 3) + (r & 7);
        Wp[(size_t)row * HN + k0 + tx] = tile[tx][ty + i];
    }
}

// ---------------- tf32 mma GEMM with cp.async double-buffer ----------------
// A: [16384 x K] tf32-rounded row-major, Bw: [K x 4096] tf32-rounded row-major.
// C scatter: row m -> (m&511)*32 + (m>>9) in [T][B][4H]. Block 128x128, 8 warps.
__global__ void __launch_bounds__(256, 1) gemm_xg_cp(
    const float* __restrict__ A, const float* __restrict__ Bw,
    const float* __restrict__ bias, float* __restrict__ C, int K)
{
    extern __shared__ char gsm[];
    const uint32_t sb = smem_u32(gsm);

    const int tid = threadIdx.x;
    const int bx = blockIdx.x;          // n tile
    const int by = blockIdx.y;          // m tile
    const int wid = tid >> 5;
    const int lane = tid & 31;
    const int g = lane >> 2, tg = lane & 3;
    const int wm = wid & 1, wn = wid >> 1;
    const int m0w = wm * 64, n0w = wn * 32;
    const int KT = K >> 5;

    const int aR = tid >> 3, aKc = tid & 7;      // A: row aR+32i, 16B col aKc
    const int bR = tid >> 5, bNc = tid & 31;     // B: k-row bR+8i, 16B col bNc

    float acc[4][4][4];
#pragma unroll
    for (int a = 0; a < 4; a++)
#pragma unroll
        for (int b = 0; b < 4; b++)
#pragma unroll
            for (int cix = 0; cix < 4; cix++) acc[a][b][cix] = 0.f;

    // ---- async stage issue ----
    auto issue = [&](int kt, int buf) {
        const uint32_t as = sb + buf * STG;
        const uint32_t bs = as + ABYT;
#pragma unroll
        for (int it = 0; it < 4; it++) {
            int row = it * 32 + aR;
            uint32_t doff = row * 128 + ((aKc * 16) ^ ((row & 7) << 4));
            cp16(as + doff, A + (size_t)(by * 128 + row) * K + kt * 32 + aKc * 4);
        }
#pragma unroll
        for (int it = 0; it < 4; it++) {
            int kr = it * 8 + bR;
            cp16(bs + kr * 544 + bNc * 16,
                 Bw + (size_t)(kt * 32 + kr) * G4H + bx * 128 + bNc * 4);
        }
        cp_commit();
    };

    issue(0, 0);
    for (int kt = 0; kt < KT; kt++) {
        const int buf = kt & 1;
        if (kt + 1 < KT) {
            issue(kt + 1, (kt + 1) & 1);
            asm volatile("cp.async.wait_group 1;" ::: "memory");
        } else {
            asm volatile("cp.async.wait_group 0;" ::: "memory");
        }
        __syncthreads();

        const unsigned* As = (const unsigned*)(gsm + buf * STG);       // [128][32]
        const unsigned* Bs = (const unsigned*)(gsm + buf * STG + ABYT); // [32][136]
#pragma unroll
        for (int s = 0; s < 4; s++) {
            unsigned af[4][4], bf[4][2];
            const int c0 = (8 * s + tg) ^ (g << 2);
            const int c1 = c0 ^ 4;
#pragma unroll
            for (int mb = 0; mb < 4; mb++) {
                int m = m0w + mb * 16 + g;
                af[mb][0] = As[m * 32 + c0];
                af[mb][1] = As[(m + 8) * 32 + c0];
                af[mb][2] = As[m * 32 + c1];
                af[mb][3] = As[(m + 8) * 32 + c1];
            }
#pragma unroll
            for (int nb = 0; nb < 4; nb++) {
                bf[nb][0] = Bs[(8 * s + tg) * 136 + n0w + nb * 8 + g];
                bf[nb][1] = Bs[(8 * s + tg + 4) * 136 + n0w + nb * 8 + g];
            }
#pragma unroll
            for (int mb = 0; mb < 4; mb++)
#pragma unroll
                for (int nb = 0; nb < 4; nb++)
                    mma_tf32(acc[mb][nb], af[mb], bf[nb]);
        }
        __syncthreads();
    }

    // epilogue: bias add + scatter to [T][B][4H]
#pragma unroll
    for (int mb = 0; mb < 4; mb++) {
        int m1 = by * 128 + m0w + mb * 16 + g;
        int m2 = m1 + 8;
        size_t r1 = (size_t)(((m1 & 511) << 5) + (m1 >> 9)) * G4H;
        size_t r2 = (size_t)(((m2 & 511) << 5) + (m2 >> 9)) * G4H;
#pragma unroll
        for (int nb = 0; nb < 4; nb++) {
            int n = bx * 128 + n0w + nb * 8 + 2 * tg;
            float2 bb = *(const float2*)(bias + n);
            float2 o1 = { acc[mb][nb][0] + bb.x, acc[mb][nb][1] + bb.y };
            float2 o2 = { acc[mb][nb][2] + bb.x, acc[mb][nb][3] + bb.y };
            *(float2*)(C + r1 + n) = o1;
            *(float2*)(C + r2 + n) = o2;
        }
    }
}

// ---------------- persistent LSTM layer (unchanged from R5, passing) ----------------
extern __shared__ float s_mem[];
__global__ void __launch_bounds__(256, 1) lstm_layer_persistent(
    const float* __restrict__ xg, const float* __restrict__ Wp,
    float* __restrict__ hA, float* __restrict__ hB, float* __restrict__ outb)
{
    const int tid = threadIdx.x;
    const int jj  = tid & 31;
    const int wq  = tid >> 5;
    const int nb  = blockIdx.x;

    float* Wsm = s_mem;
    float* hq0 = s_mem + 32 * WPAD;
    float* hq1 = hq0 + 32 * HQS;
    float* red = hq0;

    {
        const float4* Wg = (const float4*)(Wp + (size_t)nb * 32 * HN);
#pragma unroll
        for (int it = 0; it < 32; it++) {
            int i4  = it * 256 + tid;
            int row = i4 >> 8;
            int col = i4 & 255;
            *(float4*)(Wsm + (size_t)row * WPAD + col * 4) = Wg[i4];
        }
    }

    const int nl  = jj & 7;
    const int bq  = jj >> 3;
    const int myn = nb * 8 + nl;
    const int myb = wq * 4 + bq;
    {
        int b0 = tid >> 3, n0 = nb * 8 + (tid & 7);
        hA[b0 * HN + n0] = 0.f;
    }
    float creg = 0.f;
    __syncthreads();
    grid_bar();

    for (int t = 0; t < TLEN; t++) {
        const float* h_in  = (t & 1) ? hB : hA;
        float*       h_out = (t & 1) ? hA : hB;
        const float* xg_t  = xg + (size_t)t * BSZ * G4H;

        const float* xp = xg_t + (size_t)myb * G4H + myn;
        float xvi = xp[0];
        float xvf = xp[HN];
        float xvg = xp[2 * HN];
        float xvo = xp[3 * HN];

        unsigned long long acc2[32];
#pragma unroll
        for (int b = 0; b < 32; b++) acc2[b] = 0ull;

        float4 p[8];
#pragma unroll
        for (int i = 0; i < 8; i++) {
            int idx = i * 256 + tid;
            int b = idx >> 6, k4 = idx & 63;
            p[i] = __ldcg((const float4*)&h_in[(size_t)b * HN + k4 * 4]);
        }

#pragma unroll
        for (int q = 0; q < 4; q++) {
            float* hs = (q & 1) ? hq1 : hq0;
            __syncthreads();
#pragma unroll
            for (int i = 0; i < 8; i++) {
                int idx = i * 256 + tid;
                int b = idx >> 6, k4 = idx & 63;
                *(float4*)&hs[b * HQS + k4 * 4] = p[i];
            }
            __syncthreads();
            if (q < 3) {
#pragma unroll
                for (int i = 0; i < 8; i++) {
                    int idx = i * 256 + tid;
                    int b = idx >> 6, k4 = idx & 63;
                    p[i] = __ldcg((const float4*)
                        &h_in[(size_t)b * HN + (q + 1) * 256 + k4 * 4]);
                }
            }
            const ulonglong2* Wk = (const ulonglong2*)
                (Wsm + (size_t)jj * WPAD + q * 256 + wq * 32);
            const char* hrow = (const char*)(hs + wq * 32);
#pragma unroll
            for (int g = 0; g < 8; g++) {
                ulonglong2 wv = Wk[g];
                const char* hp = hrow + g * 16;
#pragma unroll
                for (int b = 0; b < 32; b++) {
                    ulonglong2 hv = *(const ulonglong2*)(hp + b * (HQS * 4));
                    ffma2(acc2[b], wv.x, hv.x);
                    ffma2(acc2[b], wv.y, hv.y);
                }
            }
        }

        float av[32];
#pragma unroll
        for (int b = 0; b < 32; b++) av[b] = pairsum(acc2[b]);

        __syncthreads();
        if (wq < 4) {
            float* rp = &red[(wq * 32 + jj) * RSTR];
#pragma unroll
            for (int b4 = 0; b4 < 8; b4++) {
                float4 v = { av[b4*4], av[b4*4+1], av[b4*4+2], av[b4*4+3] };
                *(float4*)&rp[b4 * 4] = v;
            }
        }
        __syncthreads();
        if (wq >= 4) {
            float* rp = &red[((wq - 4) * 32 + jj) * RSTR];
#pragma unroll
            for (int b4 = 0; b4 < 8; b4++) {
                float4 v = *(const float4*)&rp[b4 * 4];
                v.x += av[b4*4];   v.y += av[b4*4+1];
                v.z += av[b4*4+2]; v.w += av[b4*4+3];
                *(float4*)&rp[b4 * 4] = v;
            }
        }
        __syncthreads();

        float gi = xvi, gf = xvf, gg = xvg, go = xvo;
#pragma unroll
        for (int s = 0; s < 4; s++) {
            gi += red[(s * 32 +      nl) * RSTR + myb];
            gf += red[(s * 32 +  8 + nl) * RSTR + myb];
            gg += red[(s * 32 + 16 + nl) * RSTR + myb];
            go += red[(s * 32 + 24 + nl) * RSTR + myb];
        }

        float si = 1.f / (1.f + expf(-gi));
        float sf = 1.f / (1.f + expf(-gf));
        float so = 1.f / (1.f + expf(-go));
        creg = sf * creg + si * tanhf(gg);
        float hv = so * tanhf(creg);

        h_out[(size_t)myb * HN + myn] = hv;
        outb[(size_t)myb * (TLEN * HN) + (size_t)t * HN + myn] = hv;

        grid_bar();
    }
}

// ---------------- driver ----------------
extern "C" void kernel_launch(void* const* d_in, const int* in_sizes, int n_in,
                              void* d_out, int out_size) {
    const float* x   = (const float*)d_in[0];
    const float* Wx0 = (const float*)d_in[1];
    const float* Wh0 = (const float*)d_in[2];
    const float* b0  = (const float*)d_in[3];
    const float* Wx1 = (const float*)d_in[4];
    const float* Wh1 = (const float*)d_in[5];
    const float* b1  = (const float*)d_in[6];
    float* out = (float*)d_out;

    float *xg, *hseq, *wp0, *wp1, *hbuf, *atf, *btf;
    cudaGetSymbolAddress((void**)&xg,   g_xg);
    cudaGetSymbolAddress((void**)&hseq, g_hseq);
    cudaGetSymbolAddress((void**)&wp0,  g_Wp0);
    cudaGetSymbolAddress((void**)&wp1,  g_Wp1);
    cudaGetSymbolAddress((void**)&hbuf, g_h);
    cudaGetSymbolAddress((void**)&atf,  g_Atf);
    cudaGetSymbolAddress((void**)&btf,  g_Btf);

    const int SMEMB = (32 * WPAD + 2 * 32 * HQS) * (int)sizeof(float);
    cudaFuncSetAttribute(lstm_layer_persistent,
                         cudaFuncAttributeMaxDynamicSharedMemorySize, SMEMB);
    const int GSMEM = 2 * STG;
    cudaFuncSetAttribute(gemm_xg_cp,
                         cudaFuncAttributeMaxDynamicSharedMemorySize, GSMEM);

    const dim3 tpb(32, 8);

    // launch 1: dummy (shifts ncu -s 5 capture to gemm at launch #6)
    warm_kernel<<<1, 32>>>();
    // launches 2,3: recurrence weight packing
    pack_wh_kernel<<<dim3(G4H / 32, HN / 32), tpb>>>(Wh0, wp0);
    pack_wh_kernel<<<dim3(G4H / 32, HN / 32), tpb>>>(Wh1, wp1);

    // ---- layer 0 ---- (launches 4,5,6,7)
    cvt_tf32_kernel<<<(16384 * DIN / 4 + 255) / 256, 256>>>(x, atf, 16384 * DIN / 4);
    cvt_tf32_kernel<<<(DIN * G4H / 4 + 255) / 256, 256>>>(Wx0, btf, DIN * G4H / 4);
    gemm_xg_cp<<<dim3(G4H / 128, 16384 / 128), 256, GSMEM>>>(atf, btf, b0, xg, DIN);
    lstm_layer_persistent<<<NBLK, 256, SMEMB>>>(
        xg, wp0, hbuf, hbuf + BSZ * HN, hseq);

    // ---- layer 1 ----
    cvt_tf32_kernel<<<(16384 * HN / 4 + 255) / 256, 256>>>(hseq, atf, 16384 * HN / 4);
    cvt_tf32_kernel<<<(HN * G4H / 4 + 255) / 256, 256>>>(Wx1, btf, HN * G4H / 4);
    gemm_xg_cp<<<dim3(G4H / 128, 16384 / 128), 256, GSMEM>>>(atf, btf, b1, xg, HN);
    lstm_layer_persistent<<<NBLK, 256, SMEMB>>>(
        xg, wp1, hbuf, hbuf + BSZ * HN, out);
}

// round 11
// speedup vs baseline: 1.4832x; 1.0145x over previous
#include <cuda_runtime.h>
#include <cuda_bf16.h>
#include <math.h>
#include <stdint.h>

// Problem dims (fixed)
#define BSZ  32
#define TLEN 512
#define DIN  512
#define HN   1024
#define G4H  (4*HN)   // 4096

#define WPAD 1028      // W smem row stride (floats) for recurrence
#define HQS  260       // h quarter-row stride (floats)
#define RSTR 36        // reduction col stride (floats)
#define NBLK 128       // persistent grid size (1 CTA/SM)

// GEMM staging (bytes)
#define ABYT 16384     // As: 128 rows x 128B
#define BBYT 17408     // Bs: 32 rows x 544B (136 floats, pad 8)
#define STG  (ABYT + BBYT)

// ---------------- scratch (device globals; no allocation allowed) ----------------
__device__ float g_xg[(size_t)TLEN * BSZ * G4H];   // [T][B][4H]  256 MB
__device__ float g_hseq[(size_t)BSZ * TLEN * HN];  // [B][T][H]    64 MB
__device__ float g_Wp0[(size_t)G4H * HN];          // packed Wh0 (recurrence)
__device__ float g_Wp1[(size_t)G4H * HN];          // packed Wh1
__device__ float g_h[2][BSZ * HN];                 // ping-pong h
__device__ unsigned g_cnt;
__device__ volatile unsigned g_gen;
__device__ float g_Atf[(size_t)16384 * 1024];      // tf32-rounded A   64 MB
__device__ float g_Btf[(size_t)1024 * G4H];        // tf32-rounded W   16 MB

// ---------------- grid-wide barrier ----------------
__device__ __forceinline__ void grid_bar() {
    __threadfence();
    __syncthreads();
    if (threadIdx.x == 0) {
        unsigned my = g_gen;
        if (atomicAdd(&g_cnt, 1u) == (unsigned)(gridDim.x - 1)) {
            g_cnt = 0;
            __threadfence();
            g_gen = my + 1;
        } else {
            while (g_gen == my) { }
        }
        __threadfence();
    }
    __syncthreads();
}

// ---------------- packed dual-fp32 FMA (recurrence) ----------------
__device__ __forceinline__ void ffma2(unsigned long long& d,
                                      unsigned long long a,
                                      unsigned long long b) {
    asm("fma.rn.f32x2 %0, %1, %2, %3;" : "=l"(d) : "l"(a), "l"(b), "l"(d));
}
__device__ __forceinline__ float pairsum(unsigned long long v) {
    return __uint_as_float((unsigned)(v & 0xffffffffull)) +
           __uint_as_float((unsigned)(v >> 32));
}

// ---------------- tf32 + cp.async helpers ----------------
__device__ __forceinline__ unsigned f2tf(float f) {
    unsigned u; asm("cvt.rna.tf32.f32 %0, %1;" : "=r"(u) : "f"(f)); return u;
}
__device__ __forceinline__ void mma_tf32(float* c, const unsigned* a, const unsigned* b) {
    asm volatile(
        "mma.sync.aligned.m16n8k8.row.col.f32.tf32.tf32.f32 "
        "{%0,%1,%2,%3}, {%4,%5,%6,%7}, {%8,%9}, {%0,%1,%2,%3};\n"
        : "+f"(c[0]), "+f"(c[1]), "+f"(c[2]), "+f"(c[3])
        : "r"(a[0]), "r"(a[1]), "r"(a[2]), "r"(a[3]), "r"(b[0]), "r"(b[1]));
}
__device__ __forceinline__ uint32_t smem_u32(const void* p) {
    uint32_t a;
    asm("{ .reg .u64 t; cvta.to.shared.u64 t, %1; cvt.u32.u64 %0, t; }"
        : "=r"(a) : "l"(p));
    return a;
}
__device__ __forceinline__ void cp16(uint32_t d, const void* s) {
    asm volatile("cp.async.cg.shared.global [%0], [%1], 16;" :: "r"(d), "l"(s));
}
__device__ __forceinline__ void cp_commit() {
    asm volatile("cp.async.commit_group;" ::: "memory");
}

// ---------------- prep: round fp32 -> tf32 ----------------
__global__ void cvt_tf32_kernel(const float* __restrict__ in,
                                float* __restrict__ out, int n4) {
    int i = blockIdx.x * blockDim.x + threadIdx.x;
    if (i >= n4) return;
    float4 v = *(const float4*)(in + (size_t)i * 4);
    v.x = __uint_as_float(f2tf(v.x));
    v.y = __uint_as_float(f2tf(v.y));
    v.z = __uint_as_float(f2tf(v.z));
    v.w = __uint_as_float(f2tf(v.w));
    *(float4*)(out + (size_t)i * 4) = v;
}

// ---------------- pack Wh [K=1024][4096] -> Wp[row][k] (recurrence) ----------------
__global__ void pack_wh_kernel(const float* __restrict__ Wh, float* __restrict__ Wp) {
    __shared__ float tile[32][33];
    const int c0 = blockIdx.x * 32;
    const int k0 = blockIdx.y * 32;
    const int tx = threadIdx.x, ty = threadIdx.y;
#pragma unroll
    for (int i = 0; i < 32; i += 8)
        tile[ty + i][tx] = Wh[(size_t)(k0 + ty + i) * G4H + c0 + tx];
    __syncthreads();
#pragma unroll
    for (int i = 0; i < 32; i += 8) {
        int c  = c0 + ty + i;
        int g  = c >> 10;
        int r  = c & (HN - 1);
        int row = ((r >> 3) << 5) + (g << 3) + (r & 7);
        Wp[(size_t)row * HN + k0 + tx] = tile[tx][ty + i];
    }
}

// ---------------- tf32 mma GEMM, cp.async double-buffer, 2 CTAs/SM ----------------
// A: [16384 x K] tf32-rounded row-major, Bw: [K x 4096] tf32-rounded row-major.
// C scatter: row m -> (m&511)*32 + (m>>9) in [T][B][4H]. Block 128x128, 8 warps.
__global__ void __launch_bounds__(256, 2) gemm_xg_cp(
    const float* __restrict__ A, const float* __restrict__ Bw,
    const float* __restrict__ bias, float* __restrict__ C, int K)
{
    extern __shared__ char gsm[];
    const uint32_t sb = smem_u32(gsm);

    const int tid = threadIdx.x;
    const int bx = blockIdx.x;          // n tile
    const int by = blockIdx.y;          // m tile
    const int wid = tid >> 5;
    const int lane = tid & 31;
    const int g = lane >> 2, tg = lane & 3;
    const int wm = wid & 1, wn = wid >> 1;
    const int m0w = wm * 64, n0w = wn * 32;
    const int KT = K >> 5;

    const int aR = tid >> 3, aKc = tid & 7;      // A: row aR+32i, 16B col aKc
    const int bR = tid >> 5, bNc = tid & 31;     // B: k-row bR+8i, 16B col bNc

    float acc[4][4][4];
#pragma unroll
    for (int a = 0; a < 4; a++)
#pragma unroll
        for (int b = 0; b < 4; b++)
#pragma unroll
            for (int cix = 0; cix < 4; cix++) acc[a][b][cix] = 0.f;

    auto issue = [&](int kt, int buf) {
        const uint32_t as = sb + buf * STG;
        const uint32_t bs = as + ABYT;
#pragma unroll
        for (int it = 0; it < 4; it++) {
            int row = it * 32 + aR;
            uint32_t doff = row * 128 + ((aKc * 16) ^ ((row & 7) << 4));
            cp16(as + doff, A + (size_t)(by * 128 + row) * K + kt * 32 + aKc * 4);
        }
#pragma unroll
        for (int it = 0; it < 4; it++) {
            int kr = it * 8 + bR;
            cp16(bs + kr * 544 + bNc * 16,
                 Bw + (size_t)(kt * 32 + kr) * G4H + bx * 128 + bNc * 4);
        }
        cp_commit();
    };

    issue(0, 0);
    for (int kt = 0; kt < KT; kt++) {
        const int buf = kt & 1;
        if (kt + 1 < KT) {
            issue(kt + 1, (kt + 1) & 1);
            asm volatile("cp.async.wait_group 1;" ::: "memory");
        } else {
            asm volatile("cp.async.wait_group 0;" ::: "memory");
        }
        __syncthreads();

        const unsigned* As = (const unsigned*)(gsm + buf * STG);        // [128][32]
        const unsigned* Bs = (const unsigned*)(gsm + buf * STG + ABYT); // [32][136]
#pragma unroll
        for (int s = 0; s < 4; s++) {
            unsigned af[4][4], bf[4][2];
            const int c0 = (8 * s + tg) ^ (g << 2);
            const int c1 = c0 ^ 4;
#pragma unroll
            for (int mb = 0; mb < 4; mb++) {
                int m = m0w + mb * 16 + g;
                af[mb][0] = As[m * 32 + c0];
                af[mb][1] = As[(m + 8) * 32 + c0];
                af[mb][2] = As[m * 32 + c1];
                af[mb][3] = As[(m + 8) * 32 + c1];
            }
#pragma unroll
            for (int nb = 0; nb < 4; nb++) {
                bf[nb][0] = Bs[(8 * s + tg) * 136 + n0w + nb * 8 + g];
                bf[nb][1] = Bs[(8 * s + tg + 4) * 136 + n0w + nb * 8 + g];
            }
#pragma unroll
            for (int mb = 0; mb < 4; mb++)
#pragma unroll
                for (int nb = 0; nb < 4; nb++)
                    mma_tf32(acc[mb][nb], af[mb], bf[nb]);
        }
        __syncthreads();
    }

    // epilogue: bias add + scatter to [T][B][4H]
#pragma unroll
    for (int mb = 0; mb < 4; mb++) {
        int m1 = by * 128 + m0w + mb * 16 + g;
        int m2 = m1 + 8;
        size_t r1 = (size_t)(((m1 & 511) << 5) + (m1 >> 9)) * G4H;
        size_t r2 = (size_t)(((m2 & 511) << 5) + (m2 >> 9)) * G4H;
#pragma unroll
        for (int nb = 0; nb < 4; nb++) {
            int n = bx * 128 + n0w + nb * 8 + 2 * tg;
            float2 bb = *(const float2*)(bias + n);
            float2 o1 = { acc[mb][nb][0] + bb.x, acc[mb][nb][1] + bb.y };
            float2 o2 = { acc[mb][nb][2] + bb.x, acc[mb][nb][3] + bb.y };
            *(float2*)(C + r1 + n) = o1;
            *(float2*)(C + r2 + n) = o2;
        }
    }
}

// ---------------- persistent LSTM layer (unchanged, passing) ----------------
extern __shared__ float s_mem[];
__global__ void __launch_bounds__(256, 1) lstm_layer_persistent(
    const float* __restrict__ xg, const float* __restrict__ Wp,
    float* __restrict__ hA, float* __restrict__ hB, float* __restrict__ outb)
{
    const int tid = threadIdx.x;
    const int jj  = tid & 31;
    const int wq  = tid >> 5;
    const int nb  = blockIdx.x;

    float* Wsm = s_mem;
    float* hq0 = s_mem + 32 * WPAD;
    float* hq1 = hq0 + 32 * HQS;
    float* red = hq0;

    {
        const float4* Wg = (const float4*)(Wp + (size_t)nb * 32 * HN);
#pragma unroll
        for (int it = 0; it < 32; it++) {
            int i4  = it * 256 + tid;
            int row = i4 >> 8;
            int col = i4 & 255;
            *(float4*)(Wsm + (size_t)row * WPAD + col * 4) = Wg[i4];
        }
    }

    const int nl  = jj & 7;
    const int bq  = jj >> 3;
    const int myn = nb * 8 + nl;
    const int myb = wq * 4 + bq;
    {
        int b0 = tid >> 3, n0 = nb * 8 + (tid & 7);
        hA[b0 * HN + n0] = 0.f;
    }
    float creg = 0.f;
    __syncthreads();
    grid_bar();

    for (int t = 0; t < TLEN; t++) {
        const float* h_in  = (t & 1) ? hB : hA;
        float*       h_out = (t & 1) ? hA : hB;
        const float* xg_t  = xg + (size_t)t * BSZ * G4H;

        const float* xp = xg_t + (size_t)myb * G4H + myn;
        float xvi = xp[0];
        float xvf = xp[HN];
        float xvg = xp[2 * HN];
        float xvo = xp[3 * HN];

        unsigned long long acc2[32];
#pragma unroll
        for (int b = 0; b < 32; b++) acc2[b] = 0ull;

        float4 p[8];
#pragma unroll
        for (int i = 0; i < 8; i++) {
            int idx = i * 256 + tid;
            int b = idx >> 6, k4 = idx & 63;
            p[i] = __ldcg((const float4*)&h_in[(size_t)b * HN + k4 * 4]);
        }

#pragma unroll
        for (int q = 0; q < 4; q++) {
            float* hs = (q & 1) ? hq1 : hq0;
            __syncthreads();
#pragma unroll
            for (int i = 0; i < 8; i++) {
                int idx = i * 256 + tid;
                int b = idx >> 6, k4 = idx & 63;
                *(float4*)&hs[b * HQS + k4 * 4] = p[i];
            }
            __syncthreads();
            if (q < 3) {
#pragma unroll
                for (int i = 0; i < 8; i++) {
                    int idx = i * 256 + tid;
                    int b = idx >> 6, k4 = idx & 63;
                    p[i] = __ldcg((const float4*)
                        &h_in[(size_t)b * HN + (q + 1) * 256 + k4 * 4]);
                }
            }
            const ulonglong2* Wk = (const ulonglong2*)
                (Wsm + (size_t)jj * WPAD + q * 256 + wq * 32);
            const char* hrow = (const char*)(hs + wq * 32);
#pragma unroll
            for (int g = 0; g < 8; g++) {
                ulonglong2 wv = Wk[g];
                const char* hp = hrow + g * 16;
#pragma unroll
                for (int b = 0; b < 32; b++) {
                    ulonglong2 hv = *(const ulonglong2*)(hp + b * (HQS * 4));
                    ffma2(acc2[b], wv.x, hv.x);
                    ffma2(acc2[b], wv.y, hv.y);
                }
            }
        }

        float av[32];
#pragma unroll
        for (int b = 0; b < 32; b++) av[b] = pairsum(acc2[b]);

        __syncthreads();
        if (wq < 4) {
            float* rp = &red[(wq * 32 + jj) * RSTR];
#pragma unroll
            for (int b4 = 0; b4 < 8; b4++) {
                float4 v = { av[b4*4], av[b4*4+1], av[b4*4+2], av[b4*4+3] };
                *(float4*)&rp[b4 * 4] = v;
            }
        }
        __syncthreads();
        if (wq >= 4) {
            float* rp = &red[((wq - 4) * 32 + jj) * RSTR];
#pragma unroll
            for (int b4 = 0; b4 < 8; b4++) {
                float4 v = *(const float4*)&rp[b4 * 4];
                v.x += av[b4*4];   v.y += av[b4*4+1];
                v.z += av[b4*4+2]; v.w += av[b4*4+3];
                *(float4*)&rp[b4 * 4] = v;
            }
        }
        __syncthreads();

        float gi = xvi, gf = xvf, gg = xvg, go = xvo;
#pragma unroll
        for (int s = 0; s < 4; s++) {
            gi += red[(s * 32 +      nl) * RSTR + myb];
            gf += red[(s * 32 +  8 + nl) * RSTR + myb];
            gg += red[(s * 32 + 16 + nl) * RSTR + myb];
            go += red[(s * 32 + 24 + nl) * RSTR + myb];
        }

        float si = 1.f / (1.f + expf(-gi));
        float sf = 1.f / (1.f + expf(-gf));
        float so = 1.f / (1.f + expf(-go));
        creg = sf * creg + si * tanhf(gg);
        float hv = so * tanhf(creg);

        h_out[(size_t)myb * HN + myn] = hv;
        outb[(size_t)myb * (TLEN * HN) + (size_t)t * HN + myn] = hv;

        grid_bar();
    }
}

// ---------------- driver ----------------
extern "C" void kernel_launch(void* const* d_in, const int* in_sizes, int n_in,
                              void* d_out, int out_size) {
    const float* x   = (const float*)d_in[0];
    const float* Wx0 = (const float*)d_in[1];
    const float* Wh0 = (const float*)d_in[2];
    const float* b0  = (const float*)d_in[3];
    const float* Wx1 = (const float*)d_in[4];
    const float* Wh1 = (const float*)d_in[5];
    const float* b1  = (const float*)d_in[6];
    float* out = (float*)d_out;

    float *xg, *hseq, *wp0, *wp1, *hbuf, *atf, *btf;
    cudaGetSymbolAddress((void**)&xg,   g_xg);
    cudaGetSymbolAddress((void**)&hseq, g_hseq);
    cudaGetSymbolAddress((void**)&wp0,  g_Wp0);
    cudaGetSymbolAddress((void**)&wp1,  g_Wp1);
    cudaGetSymbolAddress((void**)&hbuf, g_h);
    cudaGetSymbolAddress((void**)&atf,  g_Atf);
    cudaGetSymbolAddress((void**)&btf,  g_Btf);

    const int SMEMB = (32 * WPAD + 2 * 32 * HQS) * (int)sizeof(float);
    cudaFuncSetAttribute(lstm_layer_persistent,
                         cudaFuncAttributeMaxDynamicSharedMemorySize, SMEMB);
    const int GSMEM = 2 * STG;
    cudaFuncSetAttribute(gemm_xg_cp,
                         cudaFuncAttributeMaxDynamicSharedMemorySize, GSMEM);

    const dim3 tpb(32, 8);

    // launch order chosen so the ncu capture (landed on my #4 last round)
    // hits gemm0 this round: cvtA(1), cvtW(2), pack0(3), gemm0(4), ...
    cvt_tf32_kernel<<<(16384 * DIN / 4 + 255) / 256, 256>>>(x, atf, 16384 * DIN / 4);
    cvt_tf32_kernel<<<(DIN * G4H / 4 + 255) / 256, 256>>>(Wx0, btf, DIN * G4H / 4);
    pack_wh_kernel<<<dim3(G4H / 32, HN / 32), tpb>>>(Wh0, wp0);
    gemm_xg_cp<<<dim3(G4H / 128, 16384 / 128), 256, GSMEM>>>(atf, btf, b0, xg, DIN);
    pack_wh_kernel<<<dim3(G4H / 32, HN / 32), tpb>>>(Wh1, wp1);
    lstm_layer_persistent<<<NBLK, 256, SMEMB>>>(
        xg, wp0, hbuf, hbuf + BSZ * HN, hseq);

    // ---- layer 1 ----
    cvt_tf32_kernel<<<(16384 * HN / 4 + 255) / 256, 256>>>(hseq, atf, 16384 * HN / 4);
    cvt_tf32_kernel<<<(HN * G4H / 4 + 255) / 256, 256>>>(Wx1, btf, HN * G4H / 4);
    gemm_xg_cp<<<dim3(G4H / 128, 16384 / 128), 256, GSMEM>>>(atf, btf, b1, xg, HN);
    lstm_layer_persistent<<<NBLK, 256, SMEMB>>>(
        xg, wp1, hbuf, hbuf + BSZ * HN, out);
}